// round 14
// baseline (speedup 1.0000x reference)
#include <cuda_runtime.h>
#include <cuda_fp16.h>
#include <cstdint>

// Problem dims (fixed by reference)
constexpr int BB = 2;
constexpr int HH = 16;
constexpr int SS = 2048;
constexpr int DD = 64;

constexpr int BR = 64;        // query rows per CTA
constexpr int BC = 64;        // keys per tile
constexpr int NTILES = SS / BC;   // 32
constexpr int NTHREADS = 256;

constexpr int LDK = 72;                 // smem leading dim (fp16), 144B rows
constexpr int QTILE = BR * LDK;         // 4608 elems
constexpr int KTILE = BC * LDK;         // 4608 elems
// smem (fp16 elems): QH | QL | KH[2] | KL[2] | VH[2]
constexpr int OFF_QH = 0;
constexpr int OFF_QL = QTILE;
constexpr int OFF_KH = 2 * QTILE;            //  9216 (2 bufs)
constexpr int OFF_KL = OFF_KH + 2 * KTILE;   // 18432 (2 bufs)
constexpr int OFF_VH = OFF_KL + 2 * KTILE;   // 27648 (2 bufs)
constexpr int SMEM_ELEMS = OFF_VH + 2 * KTILE;   // 36864
constexpr int SMEM_BYTES = SMEM_ELEMS * 2;       // 73728 -> 3 CTAs/SM

constexpr size_t KVELEMS = (size_t)BB * HH * SS * DD;   // 4 Mi
constexpr int N4KV = (int)(KVELEMS / 4);
constexpr int N4G  = (BB * SS * SS) / 4;

constexpr float PSCALE  = 9.765625e-4f;   // 2^-10 (P pack scale)
constexpr float PSCALEI = 1024.0f;

// Precomputed tensors
__device__ float g_buf[(size_t)BB * SS * SS];   // exp(dwm/sigma^2) * 0.125
__device__ __half KHg[KVELEMS];
__device__ __half KLg[KVELEMS];
__device__ __half VHg[KVELEMS];

// ---------------------------------------------------------------------------
__device__ __forceinline__ uint32_t pack2h(float a, float b) {
    __half2 t = __floats2half2_rn(a, b);
    return *reinterpret_cast<uint32_t*>(&t);
}
// hi/lo fp16x2 split of a float pair
__device__ __forceinline__ void split2h(float a, float b, uint32_t& hi, uint32_t& lo) {
    hi = pack2h(a, b);
    __half2 h = *reinterpret_cast<__half2*>(&hi);
    lo = pack2h(a - __low2float(h), b - __high2float(h));
}

// ---------------------------------------------------------------------------
// Fused prep: K -> KH/KL fp16, V -> VH fp16, g = exp(dwm/sigma^2) * 0.125.
// ---------------------------------------------------------------------------
__global__ void prep_kernel(const float* __restrict__ dwm,
                            const float* __restrict__ sigma,
                            const float* __restrict__ k,
                            const float* __restrict__ v)
{
    int idx    = blockIdx.x * blockDim.x + threadIdx.x;
    int stride = gridDim.x * blockDim.x;

    const float4* k4 = (const float4*)k;
    const float4* v4 = (const float4*)v;
    uint2* kh = (uint2*)KHg; uint2* kl = (uint2*)KLg;
    uint2* vh = (uint2*)VHg;
    for (int i = idx; i < N4KV; i += stride) {
        float4 x = k4[i];
        uint2 h, l;
        split2h(x.x, x.y, h.x, l.x);
        split2h(x.z, x.w, h.y, l.y);
        kh[i] = h; kl[i] = l;
        float4 y = v4[i];
        vh[i] = make_uint2(pack2h(y.x, y.y), pack2h(y.z, y.w));
    }

    float sg = sigma[0];
    float inv = 1.0f / (sg * sg);
    const float4* in = (const float4*)dwm;
    float4* g4 = (float4*)g_buf;
    for (int i = idx; i < N4G; i += stride) {
        float4 d = in[i];
        float4 o;
        o.x = expf(d.x * inv) * 0.125f;
        o.y = expf(d.y * inv) * 0.125f;
        o.z = expf(d.z * inv) * 0.125f;
        o.w = expf(d.w * inv) * 0.125f;
        g4[i] = o;
    }
}

// ---------------------------------------------------------------------------
__device__ __forceinline__ void mma16816(float* c, const uint32_t* a, const uint32_t* b) {
    asm volatile(
        "mma.sync.aligned.m16n8k16.row.col.f32.f16.f16.f32 "
        "{%0,%1,%2,%3}, {%4,%5,%6,%7}, {%8,%9}, {%0,%1,%2,%3};\n"
        : "+f"(c[0]), "+f"(c[1]), "+f"(c[2]), "+f"(c[3])
        : "r"(a[0]), "r"(a[1]), "r"(a[2]), "r"(a[3]), "r"(b[0]), "r"(b[1]));
}
__device__ __forceinline__ void ldsm4(uint32_t& r0, uint32_t& r1, uint32_t& r2,
                                      uint32_t& r3, uint32_t addr) {
    asm volatile("ldmatrix.sync.aligned.m8n8.x4.shared.b16 {%0,%1,%2,%3},[%4];\n"
                 : "=r"(r0), "=r"(r1), "=r"(r2), "=r"(r3) : "r"(addr));
}
__device__ __forceinline__ void ldsm4t(uint32_t& r0, uint32_t& r1, uint32_t& r2,
                                       uint32_t& r3, uint32_t addr) {
    asm volatile("ldmatrix.sync.aligned.m8n8.x4.trans.shared.b16 {%0,%1,%2,%3},[%4];\n"
                 : "=r"(r0), "=r"(r1), "=r"(r2), "=r"(r3) : "r"(addr));
}
__device__ __forceinline__ void cpa16(uint32_t dst, const void* src) {
    asm volatile("cp.async.cg.shared.global [%0], [%1], 16;\n"
                 :: "r"(dst), "l"(src));
}
__device__ __forceinline__ void prefetchL1(const void* p) {
    asm volatile("prefetch.global.L1 [%0];" :: "l"(p));
}

// ---------------------------------------------------------------------------
// Flash attention, fp16 mma.sync, 3 CTAs/SM, cross-tile software pipeline:
//   iter t: [wait cp; barrier; issue K(t+2),V(t+1)] exp(t) ; { QK(t+1) || PV(t) }
// QK: 3-product fp16 hi/lo. PV: single fp16 (P*2^-10, V hi).
// Warp w: wr=w>>1 (row-16 block), wc=w&1 (key-32 half).
// ---------------------------------------------------------------------------
__global__ void __launch_bounds__(NTHREADS, 3)
attn_kernel(const float* __restrict__ q, float* __restrict__ out,
            float* __restrict__ attn)
{
    extern __shared__ __align__(128) char smem_raw[];
    __half* smB = (__half*)smem_raw;

    const int tid  = threadIdx.x;
    const int warp = tid >> 5;
    const int lane = tid & 31;
    const int gID  = lane >> 2;
    const int tig  = lane & 3;
    const int wr   = warp >> 1;       // 0..3
    const int wc   = warp & 1;        // 0..1
    const int b    = blockIdx.z;
    const int h    = blockIdx.y;
    const int row0 = blockIdx.x * BR;
    const size_t bh = (size_t)(b * HH + h);

    const float* qp = q + bh * SS * DD + (size_t)row0 * DD;
    const float* gp = g_buf + (size_t)b * SS * SS + (size_t)row0 * SS;
    float* attnp = attn + (bh * SS + row0) * (size_t)SS;
    float* outp  = out  + (bh * SS + row0) * (size_t)DD;

    // ---- stage Q (UNSCALED; 1/8 folded into g) hi/lo into smem -------------
    for (int i = tid; i < BR * (DD / 4); i += NTHREADS) {
        int r  = i >> 4;
        int c4 = (i & 15) << 2;
        float4 qv = *(const float4*)(qp + r * DD + c4);
        uint32_t hi0, lo0, hi1, lo1;
        split2h(qv.x, qv.y, hi0, lo0);
        split2h(qv.z, qv.w, hi1, lo1);
        *(uint2*)(smB + OFF_QH + r * LDK + c4) = make_uint2(hi0, hi1);
        *(uint2*)(smB + OFF_QL + r * LDK + c4) = make_uint2(lo0, lo1);
    }

    // ---- smem addresses -----------------------------------------------------
    const uint32_t sm0  = (uint32_t)__cvta_generic_to_shared(smB);
    const uint32_t qh_s = sm0 + OFF_QH * 2;
    const uint32_t ql_s = sm0 + OFF_QL * 2;
    const uint32_t kh_s = sm0 + OFF_KH * 2;
    const uint32_t kl_s = sm0 + OFF_KL * 2;
    const uint32_t vh_s = sm0 + OFF_VH * 2;

    // QK B frags (non-trans)
    const int keyc = wc * 32 + ((lane >> 4) & 1) * 8 + (lane & 7);
    const int dsel = ((lane >> 3) & 1) * 8;
    const uint32_t koff = (uint32_t)(keyc * LDK + dsel) * 2;
    // PV B frags (trans)
    const int vkeyc = wc * 32 + ((lane >> 3) & 1) * 8 + (lane & 7);
    const int vdsel = ((lane >> 4) & 1) * 8;
    const uint32_t voff = (uint32_t)(vkeyc * LDK + vdsel) * 2;
    // Q A frags (non-trans)
    const uint32_t qoff =
        (uint32_t)((wr * 16 + ((lane >> 3) & 1) * 8 + (lane & 7)) * LDK +
                   ((lane >> 4) & 1) * 8) * 2;

    // ---- g prefetch base ----------------------------------------------------
    const float* gpre = gp + (size_t)(wr * 16 + (lane & 15)) * SS + wc * 32;

    // ---- cp.async loader mapping: threads 0-191 load KH/KL/VH rows ----------
    const int tsel = tid >> 6;          // 0:KH 1:KL 2:VH 3:idle
    const int lrow = tid & 63;
    const bool isK = tsel < 2;
    const bool isV = tsel == 2;
    const __half* gKV =
        (tsel == 0 ? KHg : tsel == 1 ? KLg : VHg) + bh * SS * DD + (size_t)lrow * DD;
    const uint32_t dst0 =
        sm0 + (uint32_t)((tsel == 0 ? OFF_KH : tsel == 1 ? OFF_KL : OFF_VH) +
                         lrow * LDK) * 2;

    float oacc[8][4];
    #pragma unroll
    for (int dt = 0; dt < 8; dt++)
        #pragma unroll
        for (int j = 0; j < 4; j++) oacc[dt][j] = 0.0f;
    float rs[2] = {0.0f, 0.0f};
    float sacc[4][4];

    // ---- helpers ------------------------------------------------------------
    // One ks-chunk of QK into sacc (2 Q ldsm + 4 K ldsm + 12 mma)
    auto qk_chunk = [&](uint32_t bufB, int ks) {
        uint32_t qhf[4], qlf[4];
        ldsm4(qhf[0], qhf[1], qhf[2], qhf[3], qh_s + qoff + ks * 32);
        ldsm4(qlf[0], qlf[1], qlf[2], qlf[3], ql_s + qoff + ks * 32);
        #pragma unroll
        for (int p = 0; p < 2; p++) {
            uint32_t Bh[2][2], Bl[2][2];
            uint32_t off = bufB + koff + (uint32_t)((p * 16 * LDK + ks * 16) * 2);
            ldsm4(Bh[0][0], Bh[0][1], Bh[1][0], Bh[1][1], kh_s + off);
            ldsm4(Bl[0][0], Bl[0][1], Bl[1][0], Bl[1][1], kl_s + off);
            #pragma unroll
            for (int j = 0; j < 2; j++) {
                const int nt = 2 * p + j;
                mma16816(sacc[nt], qhf, Bh[j]);
                mma16816(sacc[nt], qhf, Bl[j]);
                mma16816(sacc[nt], qlf, Bh[j]);
            }
        }
    };
    uint32_t ph[2][4];
    // One (kt,dp) chunk of PV (1 ldsm + 2 mma)
    auto pv_chunk = [&](uint32_t bufB, int kt, int dp) {
        uint32_t off = bufB + voff + (uint32_t)((kt * 16 * LDK + dp * 16) * 2);
        uint32_t Vh0[2], Vh1[2];
        ldsm4t(Vh0[0], Vh0[1], Vh1[0], Vh1[1], vh_s + off);
        mma16816(oacc[2 * dp],     ph[kt], Vh0);
        mma16816(oacc[2 * dp + 1], ph[kt], Vh1);
    };

    // ---- prologue: K(0); QK(0); then K(1)+V(0) ------------------------------
    if (isK) {
        #pragma unroll
        for (int c = 0; c < 8; c++) cpa16(dst0 + c * 16, gKV + c * 8);
    }
    asm volatile("cp.async.commit_group;\n");
    prefetchL1(gpre);                      // g(0)
    asm volatile("cp.async.wait_group 0;\n");
    __syncthreads();                       // Q + K(0) visible

    #pragma unroll
    for (int nt = 0; nt < 4; nt++)
        #pragma unroll
        for (int j = 0; j < 4; j++) sacc[nt][j] = 0.0f;
    #pragma unroll
    for (int ks = 0; ks < 4; ks++) qk_chunk(0, ks);   // QK(0) in buf0

    if (isK) {      // K(1) -> buf1
        const __half* src = gKV + (size_t)BC * DD;
        #pragma unroll
        for (int c = 0; c < 8; c++) cpa16(dst0 + KTILE * 2 + c * 16, src + c * 8);
    }
    if (isV) {      // V(0) -> buf0
        #pragma unroll
        for (int c = 0; c < 8; c++) cpa16(dst0 + c * 16, gKV + c * 8);
    }
    asm volatile("cp.async.commit_group;\n");

    const int rA = wr * 16 + gID;
    const int rB = rA + 8;

    for (int t = 0; t < NTILES; t++) {
        // wait for {K(t+1), V(t)}; publish; prior-iter QK/PV provably done
        asm volatile("cp.async.wait_group 0;\n");
        __syncthreads();

        // issue K(t+2) -> buf[t&1], V(t+1) -> buf[(t+1)&1]
        if (isK && t + 2 < NTILES) {
            const __half* src = gKV + (size_t)(t + 2) * BC * DD;
            const uint32_t dst = dst0 + (uint32_t)(t & 1) * (KTILE * 2);
            #pragma unroll
            for (int c = 0; c < 8; c++) cpa16(dst + c * 16, src + c * 8);
        }
        if (isV && t + 1 < NTILES) {
            const __half* src = gKV + (size_t)(t + 1) * BC * DD;
            const uint32_t dst = dst0 + (uint32_t)((t + 1) & 1) * (KTILE * 2);
            #pragma unroll
            for (int c = 0; c < 8; c++) cpa16(dst + c * 16, src + c * 8);
        }
        asm volatile("cp.async.commit_group;\n");
        if (t + 1 < NTILES) prefetchL1(gpre + (t + 1) * BC);

        const int key0 = t * BC;

        // ---- exp(t): sacc (from last iter) -> p, attn, rs, ph --------------
        #pragma unroll
        for (int nt = 0; nt < 4; nt++) {
            const int cg = key0 + wc * 32 + nt * 8 + tig * 2;
            float2 gA = *(const float2*)(gp + (size_t)rA * SS + cg);
            float2 gB = *(const float2*)(gp + (size_t)rB * SS + cg);
            float p0 = __expf(fabsf(sacc[nt][0] * gA.x));
            float p1 = __expf(fabsf(sacc[nt][1] * gA.y));
            float p2 = __expf(fabsf(sacc[nt][2] * gB.x));
            float p3 = __expf(fabsf(sacc[nt][3] * gB.y));
            *(float2*)(attnp + (size_t)rA * SS + cg) = make_float2(p0, p1);
            *(float2*)(attnp + (size_t)rB * SS + cg) = make_float2(p2, p3);
            rs[0] += p0 + p1;
            rs[1] += p2 + p3;
            const int kt = nt >> 1, hf = nt & 1;
            ph[kt][hf * 2 + 0] = pack2h(p0 * PSCALE, p1 * PSCALE);
            ph[kt][hf * 2 + 1] = pack2h(p2 * PSCALE, p3 * PSCALE);
        }

        // ---- interleaved: QK(t+1) into sacc  ||  PV(t) ----------------------
        #pragma unroll
        for (int nt = 0; nt < 4; nt++)
            #pragma unroll
            for (int j = 0; j < 4; j++) sacc[nt][j] = 0.0f;

        const uint32_t bufV  = (uint32_t)(t & 1) * (KTILE * 2);
        const uint32_t bufKn = (uint32_t)((t + 1) & 1) * (KTILE * 2);
        const bool more = (t + 1 < NTILES);

        if (more) qk_chunk(bufKn, 0);
        pv_chunk(bufV, 0, 0);
        pv_chunk(bufV, 0, 1);
        if (more) qk_chunk(bufKn, 1);
        pv_chunk(bufV, 0, 2);
        pv_chunk(bufV, 0, 3);
        if (more) qk_chunk(bufKn, 2);
        pv_chunk(bufV, 1, 0);
        pv_chunk(bufV, 1, 1);
        if (more) qk_chunk(bufKn, 3);
        pv_chunk(bufV, 1, 2);
        pv_chunk(bufV, 1, 3);
        // no trailing barrier: next iteration's barrier protects buffer reuse
    }

    // ---- epilogue: combine 2 key-half partials, rowsums, normalize ---------
    __syncthreads();   // all warps out of the loop before smem overlay

    float* Ob       = (float*)smem_raw;      // [2][64][68] = 34816B < 73728
    float* rowSumSm = Ob + 2 * 64 * 68;
    float* invS     = rowSumSm + 64;

    if (tid < BR) rowSumSm[tid] = 0.0f;
    __syncthreads();

    rs[0] += __shfl_xor_sync(0xffffffffu, rs[0], 1);
    rs[0] += __shfl_xor_sync(0xffffffffu, rs[0], 2);
    rs[1] += __shfl_xor_sync(0xffffffffu, rs[1], 1);
    rs[1] += __shfl_xor_sync(0xffffffffu, rs[1], 2);
    if (tig == 0) {
        atomicAdd(&rowSumSm[rA], rs[0]);
        atomicAdd(&rowSumSm[rB], rs[1]);
    }

    {
        float* ObW = Ob + wc * (64 * 68);
        #pragma unroll
        for (int dt = 0; dt < 8; dt++) {
            const int c = dt * 8 + tig * 2;
            *(float2*)&ObW[rA * 68 + c] = make_float2(oacc[dt][0], oacc[dt][1]);
            *(float2*)&ObW[rB * 68 + c] = make_float2(oacc[dt][2], oacc[dt][3]);
        }
    }
    __syncthreads();

    if (tid < BR) invS[tid] = 1.0f / rowSumSm[tid];
    __syncthreads();

    // O accumulated with P*2^-10 -> multiply back by 1024
    for (int i = tid; i < BR * DD; i += NTHREADS) {
        const int r = i >> 6, c = i & 63;
        float o = Ob[r * 68 + c] + Ob[64 * 68 + r * 68 + c];
        outp[(size_t)r * DD + c] = o * invS[r] * PSCALEI;
    }

    // rescale this CTA's attn slice in place; reverse order so the most
    // recently written (highest) columns are revisited first while still in L2
    for (int i = BR * (SS / 4) - 1 - tid; i >= 0; i -= NTHREADS) {
        const int r  = i >> 9;
        const int c4 = (i & 511) << 2;
        float4* p4 = (float4*)(attnp + (size_t)r * SS + c4);
        float4 vv = *p4;
        const float inv = invS[r];
        vv.x *= inv; vv.y *= inv; vv.z *= inv; vv.w *= inv;
        *p4 = vv;
    }
}

// ---------------------------------------------------------------------------
extern "C" void kernel_launch(void* const* d_in, const int* in_sizes, int n_in,
                              void* d_out, int out_size)
{
    const float* q     = (const float*)d_in[0];
    const float* k     = (const float*)d_in[1];
    const float* v     = (const float*)d_in[2];
    const float* dwm   = (const float*)d_in[3];
    const float* sigma = (const float*)d_in[4];

    float* out  = (float*)d_out;                       // [B,H,S,D]
    float* attn = out + (size_t)BB * HH * SS * DD;     // [B,H,S,S]

    prep_kernel<<<4096, 256>>>(dwm, sigma, k, v);

    cudaFuncSetAttribute(attn_kernel, cudaFuncAttributeMaxDynamicSharedMemorySize,
                         SMEM_BYTES);
    dim3 grid(SS / BR, HH, BB);
    attn_kernel<<<grid, NTHREADS, SMEM_BYTES>>>(q, out, attn);

    (void)in_sizes; (void)n_in; (void)out_size;
}

// round 15
// speedup vs baseline: 1.1813x; 1.1813x over previous
#include <cuda_runtime.h>
#include <cuda_fp16.h>
#include <cstdint>

// Problem dims (fixed by reference)
constexpr int BB = 2;
constexpr int HH = 16;
constexpr int SS = 2048;
constexpr int DD = 64;

constexpr int BR = 64;        // query rows per CTA
constexpr int BC = 64;        // keys per tile
constexpr int NTILES = SS / BC;   // 32
constexpr int NTHREADS = 256;

constexpr int LDK = 72;                 // smem leading dim (fp16), 144B rows
constexpr int QTILE = BR * LDK;         // 4608 elems
constexpr int KTILE = BC * LDK;         // 4608 elems
// smem (fp16 elems): QH | QL | KH[2] | KL[2] | VH[2]
constexpr int OFF_QH = 0;
constexpr int OFF_QL = QTILE;
constexpr int OFF_KH = 2 * QTILE;            //  9216 (2 bufs)
constexpr int OFF_KL = OFF_KH + 2 * KTILE;   // 18432 (2 bufs)
constexpr int OFF_VH = OFF_KL + 2 * KTILE;   // 27648 (2 bufs)
constexpr int SMEM_ELEMS = OFF_VH + 2 * KTILE;   // 36864
constexpr int SMEM_BYTES = SMEM_ELEMS * 2;       // 73728 -> 3 CTAs/SM

constexpr size_t KVELEMS = (size_t)BB * HH * SS * DD;   // 4 Mi
constexpr int N4KV = (int)(KVELEMS / 4);
constexpr int N4G  = (BB * SS * SS) / 4;

constexpr float PSCALE  = 9.765625e-4f;   // 2^-10 (P pack scale)
constexpr float PSCALEI = 1024.0f;
constexpr float LOG2E   = 1.4426950408889634f;

// Precomputed tensors
__device__ float g_buf[(size_t)BB * SS * SS];   // exp(dwm/sigma^2) * 0.125 * log2(e)
__device__ __half KHg[KVELEMS];
__device__ __half KLg[KVELEMS];
__device__ __half VHg[KVELEMS];

// ---------------------------------------------------------------------------
__device__ __forceinline__ uint32_t pack2h(float a, float b) {
    __half2 t = __floats2half2_rn(a, b);
    return *reinterpret_cast<uint32_t*>(&t);
}
// hi/lo fp16x2 split of a float pair
__device__ __forceinline__ void split2h(float a, float b, uint32_t& hi, uint32_t& lo) {
    hi = pack2h(a, b);
    __half2 h = *reinterpret_cast<__half2*>(&hi);
    lo = pack2h(a - __low2float(h), b - __high2float(h));
}

// ---------------------------------------------------------------------------
// Fused prep: K -> KH/KL fp16, V -> VH fp16,
//             g = exp(dwm/sigma^2) * 0.125 * log2e  (exp2-ready)
// ---------------------------------------------------------------------------
__global__ void prep_kernel(const float* __restrict__ dwm,
                            const float* __restrict__ sigma,
                            const float* __restrict__ k,
                            const float* __restrict__ v)
{
    int idx    = blockIdx.x * blockDim.x + threadIdx.x;
    int stride = gridDim.x * blockDim.x;

    const float4* k4 = (const float4*)k;
    const float4* v4 = (const float4*)v;
    uint2* kh = (uint2*)KHg; uint2* kl = (uint2*)KLg;
    uint2* vh = (uint2*)VHg;
    for (int i = idx; i < N4KV; i += stride) {
        float4 x = k4[i];
        uint2 h, l;
        split2h(x.x, x.y, h.x, l.x);
        split2h(x.z, x.w, h.y, l.y);
        kh[i] = h; kl[i] = l;
        float4 y = v4[i];
        vh[i] = make_uint2(pack2h(y.x, y.y), pack2h(y.z, y.w));
    }

    float sg = sigma[0];
    float inv = 1.0f / (sg * sg);
    const float sc = 0.125f * LOG2E;
    const float4* in = (const float4*)dwm;
    float4* g4 = (float4*)g_buf;
    for (int i = idx; i < N4G; i += stride) {
        float4 d = in[i];
        float4 o;
        o.x = expf(d.x * inv) * sc;
        o.y = expf(d.y * inv) * sc;
        o.z = expf(d.z * inv) * sc;
        o.w = expf(d.w * inv) * sc;
        g4[i] = o;
    }
}

// ---------------------------------------------------------------------------
__device__ __forceinline__ void mma16816(float* c, const uint32_t* a, const uint32_t* b) {
    asm volatile(
        "mma.sync.aligned.m16n8k16.row.col.f32.f16.f16.f32 "
        "{%0,%1,%2,%3}, {%4,%5,%6,%7}, {%8,%9}, {%0,%1,%2,%3};\n"
        : "+f"(c[0]), "+f"(c[1]), "+f"(c[2]), "+f"(c[3])
        : "r"(a[0]), "r"(a[1]), "r"(a[2]), "r"(a[3]), "r"(b[0]), "r"(b[1]));
}
__device__ __forceinline__ void ldsm4(uint32_t& r0, uint32_t& r1, uint32_t& r2,
                                      uint32_t& r3, uint32_t addr) {
    asm volatile("ldmatrix.sync.aligned.m8n8.x4.shared.b16 {%0,%1,%2,%3},[%4];\n"
                 : "=r"(r0), "=r"(r1), "=r"(r2), "=r"(r3) : "r"(addr));
}
__device__ __forceinline__ void ldsm4t(uint32_t& r0, uint32_t& r1, uint32_t& r2,
                                       uint32_t& r3, uint32_t addr) {
    asm volatile("ldmatrix.sync.aligned.m8n8.x4.trans.shared.b16 {%0,%1,%2,%3},[%4];\n"
                 : "=r"(r0), "=r"(r1), "=r"(r2), "=r"(r3) : "r"(addr));
}
__device__ __forceinline__ void cpa16(uint32_t dst, const void* src) {
    asm volatile("cp.async.cg.shared.global [%0], [%1], 16;\n"
                 :: "r"(dst), "l"(src));
}
__device__ __forceinline__ void prefetchL1(const void* p) {
    asm volatile("prefetch.global.L1 [%0];" :: "l"(p));
}

// ---------------------------------------------------------------------------
// Flash attention, fp16 mma.sync, 3 CTAs/SM (R13 pipeline).
// QK: 3-product fp16 hi/lo, product-major mma order (4-apart dependent mmas).
// PV: single fp16 (P*2^-10, V hi), per-dp V hoist + cross-oacc interleave.
// Single barrier per tile; g lines L1-prefetched one full tile ahead.
// Warp w: wr=w>>1 (row-16 block), wc=w&1 (key-32 half).
// ---------------------------------------------------------------------------
__global__ void __launch_bounds__(NTHREADS, 3)
attn_kernel(const float* __restrict__ q, float* __restrict__ out,
            float* __restrict__ attn)
{
    extern __shared__ __align__(128) char smem_raw[];
    __half* smB = (__half*)smem_raw;

    const int tid  = threadIdx.x;
    const int warp = tid >> 5;
    const int lane = tid & 31;
    const int gID  = lane >> 2;
    const int tig  = lane & 3;
    const int wr   = warp >> 1;       // 0..3
    const int wc   = warp & 1;        // 0..1
    const int b    = blockIdx.z;
    const int h    = blockIdx.y;
    const int row0 = blockIdx.x * BR;
    const size_t bh = (size_t)(b * HH + h);

    const float* qp = q + bh * SS * DD + (size_t)row0 * DD;
    const float* gp = g_buf + (size_t)b * SS * SS + (size_t)row0 * SS;
    float* attnp = attn + (bh * SS + row0) * (size_t)SS;
    float* outp  = out  + (bh * SS + row0) * (size_t)DD;

    // ---- stage Q (UNSCALED; 1/8 folded into g) hi/lo into smem -------------
    for (int i = tid; i < BR * (DD / 4); i += NTHREADS) {
        int r  = i >> 4;
        int c4 = (i & 15) << 2;
        float4 qv = *(const float4*)(qp + r * DD + c4);
        uint32_t hi0, lo0, hi1, lo1;
        split2h(qv.x, qv.y, hi0, lo0);
        split2h(qv.z, qv.w, hi1, lo1);
        *(uint2*)(smB + OFF_QH + r * LDK + c4) = make_uint2(hi0, hi1);
        *(uint2*)(smB + OFF_QL + r * LDK + c4) = make_uint2(lo0, lo1);
    }

    // ---- smem addresses -----------------------------------------------------
    const uint32_t sm0  = (uint32_t)__cvta_generic_to_shared(smB);
    const uint32_t qh_s = sm0 + OFF_QH * 2;
    const uint32_t ql_s = sm0 + OFF_QL * 2;
    const uint32_t kh_s = sm0 + OFF_KH * 2;
    const uint32_t kl_s = sm0 + OFF_KL * 2;
    const uint32_t vh_s = sm0 + OFF_VH * 2;

    // QK B frags (non-trans)
    const int keyc = wc * 32 + ((lane >> 4) & 1) * 8 + (lane & 7);
    const int dsel = ((lane >> 3) & 1) * 8;
    const uint32_t koff = (uint32_t)(keyc * LDK + dsel) * 2;
    // PV B frags (trans)
    const int vkeyc = wc * 32 + ((lane >> 3) & 1) * 8 + (lane & 7);
    const int vdsel = ((lane >> 4) & 1) * 8;
    const uint32_t voff = (uint32_t)(vkeyc * LDK + vdsel) * 2;
    // Q A frags (non-trans)
    const uint32_t qoff =
        (uint32_t)((wr * 16 + ((lane >> 3) & 1) * 8 + (lane & 7)) * LDK +
                   ((lane >> 4) & 1) * 8) * 2;

    // ---- g prefetch base ----------------------------------------------------
    const float* gpre = gp + (size_t)(wr * 16 + (lane & 15)) * SS + wc * 32;

    // ---- cp.async loader mapping: threads 0-191 load KH/KL/VH rows ----------
    const int tsel = tid >> 6;          // 0:KH 1:KL 2:VH 3:idle
    const int lrow = tid & 63;
    const bool isLd = tsel < 3;
    const __half* gKV =
        (tsel == 0 ? KHg : tsel == 1 ? KLg : VHg) + bh * SS * DD + (size_t)lrow * DD;
    const uint32_t dst0 =
        sm0 + (uint32_t)((tsel == 0 ? OFF_KH : tsel == 1 ? OFF_KL : OFF_VH) +
                         lrow * LDK) * 2;

    float oacc[8][4];
    #pragma unroll
    for (int dt = 0; dt < 8; dt++)
        #pragma unroll
        for (int j = 0; j < 4; j++) oacc[dt][j] = 0.0f;
    float rs[2] = {0.0f, 0.0f};

    // prologue: issue tile 0; prefetch g lines for tile 0
    if (isLd) {
        #pragma unroll
        for (int c = 0; c < 8; c++) cpa16(dst0 + c * 16, gKV + c * 8);
    }
    asm volatile("cp.async.commit_group;\n");
    prefetchL1(gpre);
    __syncthreads();   // Q stores visible

    const int rA = wr * 16 + gID;
    const int rB = rA + 8;

    for (int t = 0; t < NTILES; t++) {
        // wait for tile t (issued one full compute-phase ago), publish to CTA
        asm volatile("cp.async.wait_group 0;\n");
        __syncthreads();               // single barrier per tile

        // issue tile t+1 into the other buffer; prefetch g(t+1) lines
        if (t + 1 < NTILES) {
            if (isLd) {
                const __half* src = gKV + (size_t)(t + 1) * BC * DD;
                const uint32_t dst = dst0 + (uint32_t)((t + 1) & 1) * (KTILE * 2);
                #pragma unroll
                for (int c = 0; c < 8; c++) cpa16(dst + c * 16, src + c * 8);
            }
            asm volatile("cp.async.commit_group;\n");
            prefetchL1(gpre + (t + 1) * BC);
        }

        const uint32_t bufB = (uint32_t)(t & 1) * (KTILE * 2);
        const int key0 = t * BC;

        // ---- S' = Q K^T : 3-product fp16 hi/lo, product-major order --------
        float sacc[4][4];
        #pragma unroll
        for (int nt = 0; nt < 4; nt++)
            #pragma unroll
            for (int j = 0; j < 4; j++) sacc[nt][j] = 0.0f;

        #pragma unroll
        for (int ks = 0; ks < 4; ks++) {
            uint32_t qhf[4], qlf[4];
            ldsm4(qhf[0], qhf[1], qhf[2], qhf[3], qh_s + qoff + ks * 32);
            ldsm4(qlf[0], qlf[1], qlf[2], qlf[3], ql_s + qoff + ks * 32);
            uint32_t Bh[4][2], Bl[4][2];
            #pragma unroll
            for (int p = 0; p < 2; p++) {
                uint32_t off = bufB + koff + (uint32_t)((p * 16 * LDK + ks * 16) * 2);
                ldsm4(Bh[2 * p][0], Bh[2 * p][1], Bh[2 * p + 1][0], Bh[2 * p + 1][1],
                      kh_s + off);
                ldsm4(Bl[2 * p][0], Bl[2 * p][1], Bl[2 * p + 1][0], Bl[2 * p + 1][1],
                      kl_s + off);
            }
            // product-major: dependent mmas on the same sacc[nt] are 4 apart.
            // Per-accumulator order preserved (hi*Kh, hi*Kl, lo*Kh) -> bit-identical.
            #pragma unroll
            for (int nt = 0; nt < 4; nt++) mma16816(sacc[nt], qhf, Bh[nt]);
            #pragma unroll
            for (int nt = 0; nt < 4; nt++) mma16816(sacc[nt], qhf, Bl[nt]);
            #pragma unroll
            for (int nt = 0; nt < 4; nt++) mma16816(sacc[nt], qlf, Bh[nt]);
        }

        // ---- g loads (L1-hit: prefetched a full tile ago) -------------------
        float2 gA[4], gB[4];
        #pragma unroll
        for (int nt = 0; nt < 4; nt++) {
            const int cg = key0 + wc * 32 + nt * 8 + tig * 2;
            gA[nt] = *(const float2*)(gp + (size_t)rA * SS + cg);
            gB[nt] = *(const float2*)(gp + (size_t)rB * SS + cg);
        }

        // ---- p = exp2(|s'*g2|); store fp32 attn; pack P*2^-10 fp16 ---------
        uint32_t ph[2][4];
        #pragma unroll
        for (int nt = 0; nt < 4; nt++) {
            const int cg = key0 + wc * 32 + nt * 8 + tig * 2;
            float p0 = exp2f(fabsf(sacc[nt][0] * gA[nt].x));
            float p1 = exp2f(fabsf(sacc[nt][1] * gA[nt].y));
            float p2 = exp2f(fabsf(sacc[nt][2] * gB[nt].x));
            float p3 = exp2f(fabsf(sacc[nt][3] * gB[nt].y));
            *(float2*)(attnp + (size_t)rA * SS + cg) = make_float2(p0, p1);
            *(float2*)(attnp + (size_t)rB * SS + cg) = make_float2(p2, p3);
            rs[0] += p0 + p1;
            rs[1] += p2 + p3;
            const int kt = nt >> 1, hf = nt & 1;
            ph[kt][hf * 2 + 0] = pack2h(p0 * PSCALE, p1 * PSCALE);
            ph[kt][hf * 2 + 1] = pack2h(p2 * PSCALE, p3 * PSCALE);
        }

        // ---- O += P V : single fp16; per-dp V hoist, cross-oacc interleave -
        // Per-oacc accumulation order stays kt0 then kt1 -> bit-identical.
        #pragma unroll
        for (int dp = 0; dp < 4; dp++) {
            uint32_t offA = bufB + voff + (uint32_t)((dp * 16) * 2);
            uint32_t offB = offA + (uint32_t)((16 * LDK) * 2);
            uint32_t Va0[2], Va1[2], Vb0[2], Vb1[2];
            ldsm4t(Va0[0], Va0[1], Va1[0], Va1[1], vh_s + offA);
            ldsm4t(Vb0[0], Vb0[1], Vb1[0], Vb1[1], vh_s + offB);
            mma16816(oacc[2 * dp],     ph[0], Va0);
            mma16816(oacc[2 * dp + 1], ph[0], Va1);
            mma16816(oacc[2 * dp],     ph[1], Vb0);
            mma16816(oacc[2 * dp + 1], ph[1], Vb1);
        }
        // no trailing barrier: next iteration's barrier protects buffer reuse
    }

    // ---- epilogue: combine 2 key-half partials, rowsums, normalize ---------
    __syncthreads();   // all warps out of the loop before smem overlay

    float* Ob       = (float*)smem_raw;      // [2][64][68] = 34816B < 73728
    float* rowSumSm = Ob + 2 * 64 * 68;
    float* invS     = rowSumSm + 64;

    if (tid < BR) rowSumSm[tid] = 0.0f;
    __syncthreads();

    rs[0] += __shfl_xor_sync(0xffffffffu, rs[0], 1);
    rs[0] += __shfl_xor_sync(0xffffffffu, rs[0], 2);
    rs[1] += __shfl_xor_sync(0xffffffffu, rs[1], 1);
    rs[1] += __shfl_xor_sync(0xffffffffu, rs[1], 2);
    if (tig == 0) {
        atomicAdd(&rowSumSm[rA], rs[0]);
        atomicAdd(&rowSumSm[rB], rs[1]);
    }

    {
        float* ObW = Ob + wc * (64 * 68);
        #pragma unroll
        for (int dt = 0; dt < 8; dt++) {
            const int c = dt * 8 + tig * 2;
            *(float2*)&ObW[rA * 68 + c] = make_float2(oacc[dt][0], oacc[dt][1]);
            *(float2*)&ObW[rB * 68 + c] = make_float2(oacc[dt][2], oacc[dt][3]);
        }
    }
    __syncthreads();

    if (tid < BR) invS[tid] = 1.0f / rowSumSm[tid];
    __syncthreads();

    // O accumulated with P*2^-10 -> multiply back by 1024
    for (int i = tid; i < BR * DD; i += NTHREADS) {
        const int r = i >> 6, c = i & 63;
        float o = Ob[r * 68 + c] + Ob[64 * 68 + r * 68 + c];
        outp[(size_t)r * DD + c] = o * invS[r] * PSCALEI;
    }

    // rescale this CTA's attn slice in place; reverse order so the most
    // recently written (highest) columns are revisited first while still in L2
    for (int i = BR * (SS / 4) - 1 - tid; i >= 0; i -= NTHREADS) {
        const int r  = i >> 9;
        const int c4 = (i & 511) << 2;
        float4* p4 = (float4*)(attnp + (size_t)r * SS + c4);
        float4 vv = *p4;
        const float inv = invS[r];
        vv.x *= inv; vv.y *= inv; vv.z *= inv; vv.w *= inv;
        *p4 = vv;
    }
}

// ---------------------------------------------------------------------------
extern "C" void kernel_launch(void* const* d_in, const int* in_sizes, int n_in,
                              void* d_out, int out_size)
{
    const float* q     = (const float*)d_in[0];
    const float* k     = (const float*)d_in[1];
    const float* v     = (const float*)d_in[2];
    const float* dwm   = (const float*)d_in[3];
    const float* sigma = (const float*)d_in[4];

    float* out  = (float*)d_out;                       // [B,H,S,D]
    float* attn = out + (size_t)BB * HH * SS * DD;     // [B,H,S,S]

    prep_kernel<<<4096, 256>>>(dwm, sigma, k, v);

    cudaFuncSetAttribute(attn_kernel, cudaFuncAttributeMaxDynamicSharedMemorySize,
                         SMEM_BYTES);
    dim3 grid(SS / BR, HH, BB);
    attn_kernel<<<grid, NTHREADS, SMEM_BYTES>>>(q, out, attn);

    (void)in_sizes; (void)n_in; (void)out_size;
}